// round 11
// baseline (speedup 1.0000x reference)
#include <cuda_runtime.h>
#include <cuda_bf16.h>

// SurvEMD fused forward (math: see prior rounds).
// R9->R10: software prefetch (double-buffered t/e/y loads, issued mid-compute
// of the previous iteration) to raise outstanding-load duty cycle and push
// DRAM% from ~66 toward the stream ceiling. launch_bounds(256,4) pins 4
// blocks/SM so the extra 18 live regs don't drop occupancy.

#define NBINS       64
#define BLOCK_T     256
#define GRID_B      2048
#define EXP_NEG20   2.0611536e-09f   // expf(-20.0f)
#define FULL        0xFFFFFFFFu

__device__ float    g_partials[GRID_B];
__device__ unsigned g_count;         // zero-init; reset by last block each launch

__device__ __forceinline__ float frcp(float x) {
    float r;
    asm("rcp.approx.f32 %0, %1;" : "=f"(r) : "f"(x));
    return r;
}

__global__ __launch_bounds__(BLOCK_T, 4)
void survemd_main(const float* __restrict__ y_hat,
                  const int* __restrict__ t_in,
                  const int* __restrict__ e_in,
                  float* __restrict__ out,
                  int B)
{
    const int lane = threadIdx.x & 31;
    const int s    = lane & 3;    // sub-lane within row (owns f4 indices 4c+s)
    const int g    = lane >> 2;   // row within the warp's 8-row group
    const int wid  = threadIdx.x >> 5;

    const int warpsPerBlock = BLOCK_T / 32;
    const int gwarp   = blockIdx.x * warpsPerBlock + wid;
    const int wstride = GRID_B * warpsPerBlock * 8;     // rows per grid-stride step
    const int start   = gwarp * 8;

    // per-lane element base: jp1(c,i) = (4s + i + 1) + 16c
    const float b0f = (float)(4 * s + 1);
    const float b1f = b0f + 1.0f;
    const float b2f = b0f + 2.0f;
    const float b3f = b0f + 3.0f;

    float acc = 0.0f;

    if (start < B) {
        // ---- preload first iteration ----
        int rowc = min(start + g, B - 1);
        int tr = t_in[rowc];
        int er = e_in[rowc];
        const float4* yp = (const float4*)y_hat + (size_t)rowc * 16 + s;
        float4 y0 = yp[0], y1 = yp[4], y2 = yp[8], y3 = yp[12];

        // next-iteration buffers (initialized to silence UB on final rotate)
        int   trn = 0, ern = 0;
        float4 z0 = {0,0,0,0}, z1 = {0,0,0,0}, z2 = {0,0,0,0}, z3 = {0,0,0,0};

        #pragma unroll 2
        for (int base = start; base < B; base += wstride) {
            const float vmask = ((base + g) < B) ? 1.0f : 0.0f;

            // row params
            const bool  cen = (er == 0);
            const float tf  = (float)tr;
            const float kf  = cen ? (64.0f - tf) : 1.0f;
            const float q1  = frcp(fmaf(64.0f - kf, EXP_NEG20, kf));
            const float q0  = EXP_NEG20 * q1;
            const float nq0 = -q0;
            const float dq  = q1 - q0;
            const float thr = cen ? tf : 3.0e38f;
            const float isc = cen ? 0.015625f : 1.0f;
            const float nb  = -tf * isc;
            const float ndqe = cen ? (dq * -64.0f) : -dq;

            // exps + in-lane inclusive partials (consumes y0..y3)
            float sl[4][4];
            {
                const float4 ya[4] = {y0, y1, y2, y3};
                #pragma unroll
                for (int c = 0; c < 4; c++) {
                    const float thrc = thr - 16.0f * (float)c;
                    float e0 = __expf((b0f > thrc) ? 10.0f : ya[c].x);
                    float e1 = __expf((b1f > thrc) ? 10.0f : ya[c].y);
                    float e2 = __expf((b2f > thrc) ? 10.0f : ya[c].z);
                    float e3 = __expf((b3f > thrc) ? 10.0f : ya[c].w);
                    sl[c][0] = e0;
                    sl[c][1] = sl[c][0] + e1;
                    sl[c][2] = sl[c][1] + e2;
                    sl[c][3] = sl[c][2] + e3;
                }
            }

            // ---- prefetch next iteration (warp-uniform branch) ----
            const int nbase = base + wstride;
            if (nbase < B) {
                const int nrowc = min(nbase + g, B - 1);
                trn = t_in[nrowc];
                ern = e_in[nrowc];
                const float4* np = (const float4*)y_hat + (size_t)nrowc * 16 + s;
                z0 = np[0]; z1 = np[4]; z2 = np[8]; z3 = np[12];
            }

            // exclusive quad prefixes: width-4 shfl scan per chunk + carry chain
            float E[4];
            float carry = 0.0f;
            #pragma unroll
            for (int c = 0; c < 4; c++) {
                float incl = sl[c][3];
                float v = __shfl_up_sync(FULL, incl, 1, 4);
                if (s >= 1) incl += v;
                v = __shfl_up_sync(FULL, incl, 2, 4);
                if (s >= 2) incl += v;
                const float W = __shfl_sync(FULL, incl, 3, 4);   // chunk total
                E[c] = carry + (incl - sl[c][3]);
                carry += W;
            }

            const float inv = frcp(carry);   // carry == row total

            float r = 0.0f;
            #pragma unroll
            for (int c = 0; c < 4; c++) {
                const float ecinv = E[c] * inv;
                const float hq = fmaf(16.0f * (float)c, nq0, ecinv);
                const float hb = fmaf(16.0f * (float)c, isc, nb);

                float c0 = __saturatef(fmaf(b0f, isc, hb));
                float c1 = __saturatef(fmaf(b1f, isc, hb));
                float c2 = __saturatef(fmaf(b2f, isc, hb));
                float c3 = __saturatef(fmaf(b3f, isc, hb));

                float bb0 = fmaf(c0, ndqe, fmaf(b0f, nq0, hq));
                float bb1 = fmaf(c1, ndqe, fmaf(b1f, nq0, hq));
                float bb2 = fmaf(c2, ndqe, fmaf(b2f, nq0, hq));
                float bb3 = fmaf(c3, ndqe, fmaf(b3f, nq0, hq));

                float d0 = fmaf(sl[c][0], inv, bb0);
                float d1 = fmaf(sl[c][1], inv, bb1);
                float d2 = fmaf(sl[c][2], inv, bb2);
                float d3 = fmaf(sl[c][3], inv, bb3);

                r = fmaf(d0, d0, r);
                r = fmaf(d1, d1, r);
                r = fmaf(d2, d2, r);
                r = fmaf(d3, d3, r);
            }

            acc = fmaf(vmask, r, acc);

            // rotate buffers (last-iteration rotate is dead)
            tr = trn; er = ern;
            y0 = z0; y1 = z1; y2 = z2; y3 = z3;
        }
    }

    // block reduction (warp sum covers all 8 rows' lane partials)
    #pragma unroll
    for (int off = 16; off > 0; off >>= 1)
        acc += __shfl_xor_sync(FULL, acc, off);

    __shared__ float warpSums[BLOCK_T / 32];
    if (lane == 0) warpSums[wid] = acc;
    __syncthreads();

    __shared__ bool isLast;
    if (threadIdx.x == 0) {
        float sm = 0.0f;
        #pragma unroll
        for (int i = 0; i < BLOCK_T / 32; i++) sm += warpSums[i];
        g_partials[blockIdx.x] = sm;
        __threadfence();
        unsigned ticket = atomicAdd(&g_count, 1u);
        isLast = (ticket == (unsigned)(gridDim.x - 1));
    }
    __syncthreads();

    // last block reduces all partials (deterministic order) and resets counter
    if (isLast) {
        float sm = 0.0f;
        for (int i = threadIdx.x; i < GRID_B; i += BLOCK_T)
            sm += ((volatile float*)g_partials)[i];

        #pragma unroll
        for (int off = 16; off > 0; off >>= 1)
            sm += __shfl_xor_sync(FULL, sm, off);

        __shared__ float finalSums[BLOCK_T / 32];
        if (lane == 0) finalSums[wid] = sm;
        __syncthreads();

        if (threadIdx.x == 0) {
            float tot = 0.0f;
            #pragma unroll
            for (int i = 0; i < BLOCK_T / 32; i++) tot += finalSums[i];
            out[0] = tot / (float)B;
            g_count = 0;   // reset for next graph replay
        }
    }
}

extern "C" void kernel_launch(void* const* d_in, const int* in_sizes, int n_in,
                              void* d_out, int out_size)
{
    const float* y_hat = (const float*)d_in[0];
    const int*   t     = (const int*)d_in[1];
    const int*   e     = (const int*)d_in[2];
    float*       out   = (float*)d_out;
    const int B = in_sizes[1];   // element count of t

    survemd_main<<<GRID_B, BLOCK_T>>>(y_hat, t, e, out, B);
}